// round 1
// baseline (speedup 1.0000x reference)
#include <cuda_runtime.h>
#include <cstdint>

// ---- static config ----
#define BB      16
#define AA      3
#define NC      80
#define WH      76
#define MM      32
#define EE      85                       // 5 + NC
#define CELLS   (WH * WH)                // 5776
#define CPI     (AA * CELLS)             // cells per image: 17328
#define EPI     (CPI * EE)               // elems per image: 1472880
#define NTOT    (BB * EPI)               // 23,566,080 decoded elements
#define NCELLS  (BB * CPI)               // 277,248
#define NOOBJ_OFF  NTOT
#define OBJ_OFF    (NTOT + NCELLS)

__constant__ float c_anchor_w[3] = {10.f / 8.f, 16.f / 8.f, 33.f / 8.f};  // aw/INPUTW*W
__constant__ float c_anchor_h[3] = {13.f / 8.f, 30.f / 8.f, 23.f / 8.f};
__constant__ float c_all_anchors[9][2] = {
    {10.f, 13.f}, {16.f, 30.f}, {33.f, 23.f},
    {30.f, 61.f}, {62.f, 45.f}, {59.f, 119.f},
    {116.f, 90.f}, {156.f, 198.f}, {373.f, 326.f}};

__device__ __forceinline__ float sigf(float x) {
    return 1.0f / (1.0f + expf(-x));
}

// ------------------------------------------------------------------
// Kernel 1: elementwise decode.  out[i] = f(pred[i]) depending on e = i % 85.
// ------------------------------------------------------------------
__global__ void decode_kernel(const float* __restrict__ pred,
                              float* __restrict__ out) {
    int i = blockIdx.x * blockDim.x + threadIdx.x;
    if (i >= NTOT) return;
    int r    = i % EPI;          // within-image offset
    int cell = r / EE;           // 0 .. CPI-1
    int e    = r - cell * EE;

    float x = pred[i];
    float v;
    if (e >= 4) {
        v = sigf(x);                              // conf + classes
    } else if (e == 0) {
        int h = cell % WH;                        // last spatial axis
        v = sigf(x) + (float)h;
    } else if (e == 1) {
        int w = (cell % CELLS) / WH;
        v = sigf(x) + (float)w;
    } else {
        int a = cell / CELLS;
        if (e == 2) v = expf(x) * c_anchor_w[a];
        else        v = expf(x) * c_anchor_h[a];
    }
    out[i] = v;
}

// ------------------------------------------------------------------
// Kernel 2: per-cell max IoU vs this image's 32 GT boxes -> noobj.
// Also zero-initializes obj.
// gridDim = (ceil(CPI/256), B) ; blockDim = 256
// ------------------------------------------------------------------
__global__ void noobj_kernel(const float* __restrict__ dec,
                             const float* __restrict__ gt,
                             float* __restrict__ out) {
    __shared__ float gx1[MM], gy1[MM], gx2[MM], gy2[MM], gar[MM];
    int b   = blockIdx.y;
    int tid = threadIdx.x;
    if (tid < MM) {
        const float* g = gt + (size_t)(b * MM + tid) * 6;
        float cx = g[1], cy = g[2], gw = g[3], gh = g[4];
        float x1 = (cx - gw * 0.5f) * 608.0f;
        float y1 = (cy - gh * 0.5f) * 608.0f;
        float x2 = (cx + gw * 0.5f) * 608.0f;
        float y2 = (cy + gh * 0.5f) * 608.0f;
        gx1[tid] = x1; gy1[tid] = y1; gx2[tid] = x2; gy2[tid] = y2;
        gar[tid] = (x2 - x1) * (y2 - y1);
    }
    __syncthreads();

    int c = blockIdx.x * blockDim.x + tid;
    if (c >= CPI) return;

    size_t base = (size_t)b * EPI + (size_t)c * EE;
    float px = dec[base + 0];
    float py = dec[base + 1];
    float pw = dec[base + 2];
    float ph = dec[base + 3];

    float x1 = (px - pw * 0.5f) * 8.0f;
    float y1 = (py - ph * 0.5f) * 8.0f;
    float x2 = (px + pw * 0.5f) * 8.0f;
    float y2 = (py + ph * 0.5f) * 8.0f;
    float pa = (x2 - x1) * (y2 - y1);

    float maxv = -1.0f;
#pragma unroll 8
    for (int m = 0; m < MM; m++) {
        float ix = fminf(x2, gx2[m]) - fmaxf(x1, gx1[m]);
        float iy = fminf(y2, gy2[m]) - fmaxf(y1, gy1[m]);
        ix = fmaxf(ix, 0.0f);
        iy = fmaxf(iy, 0.0f);
        float inter = ix * iy;
        float iou = inter / (pa + gar[m] - inter);
        maxv = fmaxf(maxv, iou);
    }

    int oc = b * CPI + c;
    out[NOOBJ_OFF + oc] = (maxv <= 0.5f) ? 1.0f : 0.0f;
    out[OBJ_OFF + oc]   = 0.0f;
}

// ------------------------------------------------------------------
// Kernel 3: per-GT best-anchor assignment, scatter obj / override noobj.
// <<<1, 512>>>
// ------------------------------------------------------------------
__global__ void assign_kernel(const float* __restrict__ gt,
                              float* __restrict__ out) {
    int t = blockIdx.x * blockDim.x + threadIdx.x;
    if (t >= BB * MM) return;
    const float* g = gt + (size_t)t * 6;
    float cx = g[1], cy = g[2], gw = g[3], gh = g[4];
    int b = (int)g[5];

    float gx1 = (cx - gw * 0.5f) * 608.0f;
    float gy1 = (cy - gh * 0.5f) * 608.0f;
    float gx2 = (cx + gw * 0.5f) * 608.0f;
    float gy2 = (cy + gh * 0.5f) * 608.0f;
    float gar = (gx2 - gx1) * (gy2 - gy1);

    int   best   = 0;
    float bestv  = -1.0f;
#pragma unroll
    for (int k = 0; k < 9; k++) {
        float ow = c_all_anchors[k][0] / 608.0f;   // normalized, as in reference
        float oh = c_all_anchors[k][1] / 608.0f;
        float ax1 = (cx - ow * 0.5f) * 608.0f;
        float ay1 = (cy - oh * 0.5f) * 608.0f;
        float ax2 = (cx + ow * 0.5f) * 608.0f;
        float ay2 = (cy + oh * 0.5f) * 608.0f;
        float aar = (ax2 - ax1) * (ay2 - ay1);
        float ix = fminf(gx2, ax2) - fmaxf(gx1, ax1);
        float iy = fminf(gy2, ay2) - fmaxf(gy1, ay1);
        ix = fmaxf(ix, 0.0f);
        iy = fmaxf(iy, 0.0f);
        float inter = ix * iy;
        float iou = inter / (gar + aar - inter);
        if (iou > bestv) { bestv = iou; best = k; }   // strict > : first max wins
    }

    bool valid = best < AA;
    int a  = best < AA ? best : AA - 1;
    int gi = (int)(cx * (float)WH);
    int gj = (int)(cy * (float)WH);
    int flat = ((b * AA + a) * WH + gi) * WH + gj;
    if (valid) {
        out[OBJ_OFF + flat]   = 1.0f;
        out[NOOBJ_OFF + flat] = 0.0f;
    }
}

extern "C" void kernel_launch(void* const* d_in, const int* in_sizes, int n_in,
                              void* d_out, int out_size) {
    const float* pred = (const float*)d_in[0];
    const float* gt   = (const float*)d_in[1];
    float* out = (float*)d_out;

    (void)in_sizes; (void)n_in; (void)out_size;

    {
        int threads = 256;
        int blocks = (NTOT + threads - 1) / threads;
        decode_kernel<<<blocks, threads>>>(pred, out);
    }
    {
        dim3 grid((CPI + 255) / 256, BB);
        noobj_kernel<<<grid, 256>>>(out, gt, out);
    }
    {
        assign_kernel<<<1, 512>>>(gt, out);
    }
}

// round 2
// speedup vs baseline: 1.5710x; 1.5710x over previous
#include <cuda_runtime.h>
#include <cstdint>

// ---- static config ----
#define BB      16
#define AA      3
#define NC      80
#define WH      76
#define MM      32
#define EE      85                       // 5 + NC
#define CELLS   (WH * WH)                // 5776
#define CPI     (AA * CELLS)             // cells per image: 17328
#define EPI     (CPI * EE)               // elems per image: 1472880
#define NTOT    (BB * EPI)               // 23,566,080 decoded elements
#define NV4     (NTOT / 4)               // 5,891,520 float4s
#define NCELLS  (BB * CPI)               // 277,248
#define NOOBJ_OFF  NTOT
#define OBJ_OFF    (NTOT + NCELLS)

__constant__ float c_anchor_w[3] = {10.f / 8.f, 16.f / 8.f, 33.f / 8.f};  // aw/INPUTW*W
__constant__ float c_anchor_h[3] = {13.f / 8.f, 30.f / 8.f, 23.f / 8.f};
__constant__ float c_all_anchors[9][2] = {
    {10.f, 13.f}, {16.f, 30.f}, {33.f, 23.f},
    {30.f, 61.f}, {62.f, 45.f}, {59.f, 119.f},
    {116.f, 90.f}, {156.f, 198.f}, {373.f, 326.f}};

// fast sigmoid (decode path; 1e-3 rel tolerance on output)
__device__ __forceinline__ float sigfast(float x) {
    return __fdividef(1.0f, 1.0f + __expf(-x));
}
// accurate sigmoid (threshold-feeding paths)
__device__ __forceinline__ float sigacc(float x) {
    return 1.0f / (1.0f + expf(-x));
}

// ------------------------------------------------------------------
// Kernel 1: float4-vectorized elementwise decode.
// Common path: pure sigmoid. Rare lanes (e in [0,4)) patched after.
// ------------------------------------------------------------------
__global__ void decode4_kernel(const float4* __restrict__ pred,
                               float4* __restrict__ out) {
    int t = blockIdx.x * blockDim.x + threadIdx.x;
    if (t >= NV4) return;

    float4 x = pred[t];
    float4 v;
    v.x = sigfast(x.x);
    v.y = sigfast(x.y);
    v.z = sigfast(x.z);
    v.w = sigfast(x.w);

    int base = t * 4;
    int e0   = base % EE;               // one magic-div per 4 elements

    if (e0 < 4 || e0 > (EE - 4)) {      // some lane may be special (e in 0..3)
        float xs[4] = {x.x, x.y, x.z, x.w};
        float vs[4] = {v.x, v.y, v.z, v.w};
#pragma unroll
        for (int j = 0; j < 4; j++) {
            int e = e0 + j;
            if (e >= EE) e -= EE;
            if (e < 4) {
                int idx   = base + j;
                int cellg = idx / EE;             // global cell id
                float xv  = xs[j];
                if (e == 0) {
                    int h = cellg % WH;
                    vs[j] = sigfast(xv) + (float)h;
                } else if (e == 1) {
                    int w = (cellg % CELLS) / WH;
                    vs[j] = sigfast(xv) + (float)w;
                } else {
                    int a = (cellg / CELLS) % AA;
                    float s = __expf(xv);
                    vs[j] = s * (e == 2 ? c_anchor_w[a] : c_anchor_h[a]);
                }
            }
        }
        v.x = vs[0]; v.y = vs[1]; v.z = vs[2]; v.w = vs[3];
    }
    out[t] = v;
}

// ------------------------------------------------------------------
// Kernel 2: per-cell max IoU vs this image's 32 GT boxes -> noobj.
// Reads raw pred (independent of decode). Also zero-inits obj.
// gridDim = (ceil(CPI/256), B) ; blockDim = 256
// ------------------------------------------------------------------
__global__ void noobj_kernel(const float* __restrict__ pred,
                             const float* __restrict__ gt,
                             float* __restrict__ out) {
    __shared__ float gx1[MM], gy1[MM], gx2[MM], gy2[MM], gar[MM];
    int b   = blockIdx.y;
    int tid = threadIdx.x;
    if (tid < MM) {
        const float* g = gt + (size_t)(b * MM + tid) * 6;
        float cx = g[1], cy = g[2], gw = g[3], gh = g[4];
        float x1 = (cx - gw * 0.5f) * 608.0f;
        float y1 = (cy - gh * 0.5f) * 608.0f;
        float x2 = (cx + gw * 0.5f) * 608.0f;
        float y2 = (cy + gh * 0.5f) * 608.0f;
        gx1[tid] = x1; gy1[tid] = y1; gx2[tid] = x2; gy2[tid] = y2;
        gar[tid] = (x2 - x1) * (y2 - y1);
    }
    __syncthreads();

    int c = blockIdx.x * blockDim.x + tid;
    if (c >= CPI) return;

    // decode this cell's box from raw pred (accurate math: feeds a threshold)
    size_t base = (size_t)b * EPI + (size_t)c * EE;
    float p0 = pred[base + 0];
    float p1 = pred[base + 1];
    float p2 = pred[base + 2];
    float p3 = pred[base + 3];

    int a = c / CELLS;
    int sp = c - a * CELLS;
    int w = sp / WH;
    int h = sp - w * WH;

    float px = sigacc(p0) + (float)h;
    float py = sigacc(p1) + (float)w;
    float pw = expf(p2) * c_anchor_w[a];
    float ph = expf(p3) * c_anchor_h[a];

    float x1 = (px - pw * 0.5f) * 8.0f;
    float y1 = (py - ph * 0.5f) * 8.0f;
    float x2 = (px + pw * 0.5f) * 8.0f;
    float y2 = (py + ph * 0.5f) * 8.0f;
    float pa = (x2 - x1) * (y2 - y1);

    float maxv = -1.0f;
#pragma unroll 8
    for (int m = 0; m < MM; m++) {
        float ix = fminf(x2, gx2[m]) - fmaxf(x1, gx1[m]);
        float iy = fminf(y2, gy2[m]) - fmaxf(y1, gy1[m]);
        ix = fmaxf(ix, 0.0f);
        iy = fmaxf(iy, 0.0f);
        float inter = ix * iy;
        float iou = inter / (pa + gar[m] - inter);
        maxv = fmaxf(maxv, iou);
    }

    int oc = b * CPI + c;
    out[NOOBJ_OFF + oc] = (maxv <= 0.5f) ? 1.0f : 0.0f;
    out[OBJ_OFF + oc]   = 0.0f;
}

// ------------------------------------------------------------------
// Kernel 3: per-GT best-anchor assignment, scatter obj / override noobj.
// <<<1, 512>>>
// ------------------------------------------------------------------
__global__ void assign_kernel(const float* __restrict__ gt,
                              float* __restrict__ out) {
    int t = blockIdx.x * blockDim.x + threadIdx.x;
    if (t >= BB * MM) return;
    const float* g = gt + (size_t)t * 6;
    float cx = g[1], cy = g[2], gw = g[3], gh = g[4];
    int b = (int)g[5];

    float gx1 = (cx - gw * 0.5f) * 608.0f;
    float gy1 = (cy - gh * 0.5f) * 608.0f;
    float gx2 = (cx + gw * 0.5f) * 608.0f;
    float gy2 = (cy + gh * 0.5f) * 608.0f;
    float gar = (gx2 - gx1) * (gy2 - gy1);

    int   best  = 0;
    float bestv = -1.0f;
#pragma unroll
    for (int k = 0; k < 9; k++) {
        float ow = c_all_anchors[k][0] / 608.0f;
        float oh = c_all_anchors[k][1] / 608.0f;
        float ax1 = (cx - ow * 0.5f) * 608.0f;
        float ay1 = (cy - oh * 0.5f) * 608.0f;
        float ax2 = (cx + ow * 0.5f) * 608.0f;
        float ay2 = (cy + oh * 0.5f) * 608.0f;
        float aar = (ax2 - ax1) * (ay2 - ay1);
        float ix = fminf(gx2, ax2) - fmaxf(gx1, ax1);
        float iy = fminf(gy2, ay2) - fmaxf(gy1, ay1);
        ix = fmaxf(ix, 0.0f);
        iy = fmaxf(iy, 0.0f);
        float inter = ix * iy;
        float iou = inter / (gar + aar - inter);
        if (iou > bestv) { bestv = iou; best = k; }   // strict > : first max wins
    }

    bool valid = best < AA;
    int a  = best < AA ? best : AA - 1;
    int gi = (int)(cx * (float)WH);
    int gj = (int)(cy * (float)WH);
    int flat = ((b * AA + a) * WH + gi) * WH + gj;
    if (valid) {
        out[OBJ_OFF + flat]   = 1.0f;
        out[NOOBJ_OFF + flat] = 0.0f;
    }
}

extern "C" void kernel_launch(void* const* d_in, const int* in_sizes, int n_in,
                              void* d_out, int out_size) {
    const float* pred = (const float*)d_in[0];
    const float* gt   = (const float*)d_in[1];
    float* out = (float*)d_out;

    (void)in_sizes; (void)n_in; (void)out_size;

    {
        int threads = 256;
        int blocks = (NV4 + threads - 1) / threads;
        decode4_kernel<<<blocks, threads>>>((const float4*)pred, (float4*)out);
    }
    {
        dim3 grid((CPI + 255) / 256, BB);
        noobj_kernel<<<grid, 256>>>(pred, gt, out);
    }
    {
        assign_kernel<<<1, 512>>>(gt, out);
    }
}

// round 3
// speedup vs baseline: 1.7551x; 1.1172x over previous
#include <cuda_runtime.h>
#include <cstdint>

// ---- static config ----
#define BB      16
#define AA      3
#define NC      80
#define WH      76
#define MM      32
#define EE      85                       // 5 + NC
#define CELLS   (WH * WH)                // 5776
#define CPI     (AA * CELLS)             // cells per image: 17328
#define EPI     (CPI * EE)               // elems per image: 1472880
#define NTOT    (BB * EPI)               // 23,566,080 decoded elements
#define NV4     (NTOT / 4)               // 5,891,520 float4s
#define NCELLS  (BB * CPI)               // 277,248
#define NOOBJ_OFF  NTOT
#define OBJ_OFF    (NTOT + NCELLS)

__constant__ float c_anchor_w[3] = {10.f / 8.f, 16.f / 8.f, 33.f / 8.f};  // aw/INPUTW*W
__constant__ float c_anchor_h[3] = {13.f / 8.f, 30.f / 8.f, 23.f / 8.f};
__constant__ float c_all_anchors[9][2] = {
    {10.f, 13.f}, {16.f, 30.f}, {33.f, 23.f},
    {30.f, 61.f}, {62.f, 45.f}, {59.f, 119.f},
    {116.f, 90.f}, {156.f, 198.f}, {373.f, 326.f}};

// 3-instruction sigmoid: sigma(x) = 0.5 + 0.5 * tanh(x/2) via MUFU.TANH
__device__ __forceinline__ float sigt(float x) {
    float t;
    float h = 0.5f * x;
    asm("tanh.approx.f32 %0, %1;" : "=f"(t) : "f"(h));
    return fmaf(0.5f, t, 0.5f);
}
// accurate sigmoid (values written for box lanes / threshold paths)
__device__ __forceinline__ float sigacc(float x) {
    return 1.0f / (1.0f + expf(-x));
}

// ------------------------------------------------------------------
// Kernel 1: branch-free float4 sigmoid over ALL elements.
// Box lanes (e<4) are garbage here; overwritten by cell_kernel.
// ------------------------------------------------------------------
__global__ void __launch_bounds__(256) sig_kernel(const float4* __restrict__ pred,
                                                  float4* __restrict__ out) {
    int t = blockIdx.x * blockDim.x + threadIdx.x;
    if (t >= NV4) return;
    float4 x = pred[t];
    float4 v;
    v.x = sigt(x.x);
    v.y = sigt(x.y);
    v.z = sigt(x.z);
    v.w = sigt(x.w);
    out[t] = v;
}

// ------------------------------------------------------------------
// Kernel 2 (fused): per cell —
//   * decode the 4 box elements accurately, overwrite out[base..base+3]
//   * max IoU vs this image's 32 GT boxes -> noobj
//   * zero-init obj
// gridDim = (ceil(CPI/256), B) ; blockDim = 256
// ------------------------------------------------------------------
__global__ void __launch_bounds__(256) cell_kernel(const float* __restrict__ pred,
                                                   const float* __restrict__ gt,
                                                   float* __restrict__ out) {
    __shared__ float gx1[MM], gy1[MM], gx2[MM], gy2[MM], gar[MM];
    int b   = blockIdx.y;
    int tid = threadIdx.x;
    if (tid < MM) {
        const float* g = gt + (size_t)(b * MM + tid) * 6;
        float cx = g[1], cy = g[2], gw = g[3], gh = g[4];
        float x1 = (cx - gw * 0.5f) * 608.0f;
        float y1 = (cy - gh * 0.5f) * 608.0f;
        float x2 = (cx + gw * 0.5f) * 608.0f;
        float y2 = (cy + gh * 0.5f) * 608.0f;
        gx1[tid] = x1; gy1[tid] = y1; gx2[tid] = x2; gy2[tid] = y2;
        gar[tid] = (x2 - x1) * (y2 - y1);
    }
    __syncthreads();

    int c = blockIdx.x * blockDim.x + tid;
    if (c >= CPI) return;

    size_t base = (size_t)b * EPI + (size_t)c * EE;
    float p0 = pred[base + 0];
    float p1 = pred[base + 1];
    float p2 = pred[base + 2];
    float p3 = pred[base + 3];

    int a  = c / CELLS;
    int sp = c - a * CELLS;
    int w  = sp / WH;
    int h  = sp - w * WH;

    float px = sigacc(p0) + (float)h;
    float py = sigacc(p1) + (float)w;
    float pw = expf(p2) * c_anchor_w[a];
    float ph = expf(p3) * c_anchor_h[a];

    // overwrite the decoded box lanes with accurate values
    out[base + 0] = px;
    out[base + 1] = py;
    out[base + 2] = pw;
    out[base + 3] = ph;

    float x1 = (px - pw * 0.5f) * 8.0f;
    float y1 = (py - ph * 0.5f) * 8.0f;
    float x2 = (px + pw * 0.5f) * 8.0f;
    float y2 = (py + ph * 0.5f) * 8.0f;
    float pa = (x2 - x1) * (y2 - y1);

    float maxv = -1.0f;
#pragma unroll 8
    for (int m = 0; m < MM; m++) {
        float ix = fminf(x2, gx2[m]) - fmaxf(x1, gx1[m]);
        float iy = fminf(y2, gy2[m]) - fmaxf(y1, gy1[m]);
        ix = fmaxf(ix, 0.0f);
        iy = fmaxf(iy, 0.0f);
        float inter = ix * iy;
        float iou = inter / (pa + gar[m] - inter);
        maxv = fmaxf(maxv, iou);
    }

    int oc = b * CPI + c;
    out[NOOBJ_OFF + oc] = (maxv <= 0.5f) ? 1.0f : 0.0f;
    out[OBJ_OFF + oc]   = 0.0f;
}

// ------------------------------------------------------------------
// Kernel 3: per-GT best-anchor assignment, scatter obj / override noobj.
// <<<1, 512>>>
// ------------------------------------------------------------------
__global__ void assign_kernel(const float* __restrict__ gt,
                              float* __restrict__ out) {
    int t = blockIdx.x * blockDim.x + threadIdx.x;
    if (t >= BB * MM) return;
    const float* g = gt + (size_t)t * 6;
    float cx = g[1], cy = g[2], gw = g[3], gh = g[4];
    int b = (int)g[5];

    float gx1 = (cx - gw * 0.5f) * 608.0f;
    float gy1 = (cy - gh * 0.5f) * 608.0f;
    float gx2 = (cx + gw * 0.5f) * 608.0f;
    float gy2 = (cy + gh * 0.5f) * 608.0f;
    float gar = (gx2 - gx1) * (gy2 - gy1);

    int   best  = 0;
    float bestv = -1.0f;
#pragma unroll
    for (int k = 0; k < 9; k++) {
        float ow = c_all_anchors[k][0] / 608.0f;
        float oh = c_all_anchors[k][1] / 608.0f;
        float ax1 = (cx - ow * 0.5f) * 608.0f;
        float ay1 = (cy - oh * 0.5f) * 608.0f;
        float ax2 = (cx + ow * 0.5f) * 608.0f;
        float ay2 = (cy + oh * 0.5f) * 608.0f;
        float aar = (ax2 - ax1) * (ay2 - ay1);
        float ix = fminf(gx2, ax2) - fmaxf(gx1, ax1);
        float iy = fminf(gy2, ay2) - fmaxf(gy1, ay1);
        ix = fmaxf(ix, 0.0f);
        iy = fmaxf(iy, 0.0f);
        float inter = ix * iy;
        float iou = inter / (gar + aar - inter);
        if (iou > bestv) { bestv = iou; best = k; }   // strict > : first max wins
    }

    bool valid = best < AA;
    int a  = best < AA ? best : AA - 1;
    int gi = (int)(cx * (float)WH);
    int gj = (int)(cy * (float)WH);
    int flat = ((b * AA + a) * WH + gi) * WH + gj;
    if (valid) {
        out[OBJ_OFF + flat]   = 1.0f;
        out[NOOBJ_OFF + flat] = 0.0f;
    }
}

extern "C" void kernel_launch(void* const* d_in, const int* in_sizes, int n_in,
                              void* d_out, int out_size) {
    const float* pred = (const float*)d_in[0];
    const float* gt   = (const float*)d_in[1];
    float* out = (float*)d_out;

    (void)in_sizes; (void)n_in; (void)out_size;

    {
        int threads = 256;
        int blocks = (NV4 + threads - 1) / threads;
        sig_kernel<<<blocks, threads>>>((const float4*)pred, (float4*)out);
    }
    {
        dim3 grid((CPI + 255) / 256, BB);
        cell_kernel<<<grid, 256>>>(pred, gt, out);
    }
    {
        assign_kernel<<<1, 512>>>(gt, out);
    }
}